// round 7
// baseline (speedup 1.0000x reference)
#include <cuda_runtime.h>
#include <cuda_fp16.h>
#include <cstdint>

// ============================================================
// EdgeUpdate fused MLP via legacy mma.sync (sm_103 non-'a' target).
// R7: dual phase-offset consumer groups + producer warps.
//   384 threads: warps 0-3 = group0 consumers, 4-7 = group1
//   consumers, 8-9 = group0 producers, 10-11 = group1 producers.
//   Each group owns a 64-row tile stream (parity g), double-buffered
//   X, its own H, its own named barriers. Group phases interleave on
//   each SMSP: one group's MUFU/act overlaps the other's HMMA.
// Warp tiles 32x64 (GEMM1) / 32x32 (GEMM2) — R6's low-traffic shape.
// ============================================================

#define XSTR 400   // 192 f16 + pad
#define HSTR 272   // 128 f16 + pad
#define XBUF (64 * XSTR)               // 25600 per 64-row buffer

#define SO_X   0                        // 4 buffers: [g][p] -> (2g+p)*XBUF
#define SO_W1  (4 * XBUF)               // 102400
#define SO_W2  (SO_W1 + 128 * XSTR)     // 153600
#define SO_H0  (SO_W2 + 64 * HSTR)      // 171008
#define SO_H1  (SO_H0 + 64 * HSTR)      // 188416
#define SO_B1  (SO_H1 + 64 * HSTR)      // 205824
#define SO_B2  (SO_B1 + 512)
#define SMEM_TOTAL (SO_B2 + 256 + 128)  // ~206.8 KB

#define BARX(id, cnt) \
    asm volatile("bar.sync %0, %1;" :: "r"(id), "r"(cnt) : "memory")
#define BARA(id, cnt) \
    asm volatile("bar.arrive %0, %1;" :: "r"(id), "r"(cnt) : "memory")

__device__ __forceinline__ uint32_t s2u(const void* p) {
    uint32_t a;
    asm("{ .reg .u64 t; cvta.to.shared.u64 t, %1; cvt.u32.u64 %0, t; }"
        : "=r"(a) : "l"(p));
    return a;
}

__device__ __forceinline__ uint32_t pkh2(float lo, float hi) {
    uint32_t r;
    asm("cvt.rn.f16x2.f32 %0, %1, %2;" : "=r"(r) : "f"(hi), "f"(lo));
    return r;
}

__device__ __forceinline__ void ldm4(uint32_t* r, uint32_t addr) {
    asm volatile("ldmatrix.sync.aligned.m8n8.x4.shared.b16 {%0,%1,%2,%3}, [%4];"
                 : "=r"(r[0]), "=r"(r[1]), "=r"(r[2]), "=r"(r[3]) : "r"(addr));
}

__device__ __forceinline__ void mma16816(float* d, const uint32_t* a,
                                         uint32_t b0, uint32_t b1) {
    asm volatile(
        "mma.sync.aligned.m16n8k16.row.col.f32.f16.f16.f32 "
        "{%0,%1,%2,%3}, {%4,%5,%6,%7}, {%8,%9}, {%0,%1,%2,%3};"
        : "+f"(d[0]), "+f"(d[1]), "+f"(d[2]), "+f"(d[3])
        : "r"(a[0]), "r"(a[1]), "r"(a[2]), "r"(a[3]), "r"(b0), "r"(b1));
}

// shifted softplus: softplus(x) - ln2 = max(x,0) + ln(1+e^{-|x|}) - ln2
__device__ __forceinline__ float ssp(float x) {
    float e = __expf(-fabsf(x));
    float l = __log2f(1.0f + e);
    return fmaxf(x, 0.0f) + 0.6931471805599453f * (l - 1.0f);
}

// producer: fill 32 rows (pw half) of a 64-row X buffer for `tile`
__device__ __forceinline__ void fill_half(
    uint32_t xb, long long tile, int pw, int g_half, int g_li,
    const int* __restrict__ edges, const float* __restrict__ node_state,
    const float* __restrict__ edge_state, int E) {
#pragma unroll 4
    for (int i2 = 0; i2 < 16; i2++) {
        int row = pw * 32 + i2 * 2 + g_half;
        long long e = tile * 64 + row;
        long long ec = (e < E) ? e : (long long)(E - 1);
        int2 np2 = ((const int2*)edges)[ec];
        uint32_t xr = xb + (uint32_t)row * XSTR + (uint32_t)g_li * 8u;
        float4 v0 = ((const float4*)(node_state + (long long)np2.x * 64))[g_li];
        float4 v1 = ((const float4*)(node_state + (long long)np2.y * 64))[g_li];
        float4 v2 = __ldcs((const float4*)(edge_state + ec * 64) + g_li);
        uint32_t a0 = pkh2(v0.x, v0.y), a1 = pkh2(v0.z, v0.w);
        uint32_t c0 = pkh2(v1.x, v1.y), c1 = pkh2(v1.z, v1.w);
        uint32_t d0 = pkh2(v2.x, v2.y), d1 = pkh2(v2.z, v2.w);
        asm volatile("st.shared.v2.b32 [%0], {%1,%2};"
                     :: "r"(xr), "r"(a0), "r"(a1) : "memory");
        asm volatile("st.shared.v2.b32 [%0], {%1,%2};"
                     :: "r"(xr + 128), "r"(c0), "r"(c1) : "memory");
        asm volatile("st.shared.v2.b32 [%0], {%1,%2};"
                     :: "r"(xr + 256), "r"(d0), "r"(d1) : "memory");
    }
}

__global__ void __launch_bounds__(384, 1)
edge_update_kernel(const float* __restrict__ edge_state,
                   const int* __restrict__ edges,
                   const float* __restrict__ node_state,
                   const float* __restrict__ W1, const float* __restrict__ b1,
                   const float* __restrict__ W2, const float* __restrict__ b2,
                   float* __restrict__ out, int E) {
    extern __shared__ __align__(128) char smem[];
    uint32_t sb = s2u(smem);
    int tid = threadIdx.x;
    int lane = tid & 31, w = tid >> 5;

    // ---- one-time: stage weights (f32 -> f16) + biases into SMEM ----
    for (int i = tid; i < 128 * 192; i += 384) {
        int n = i / 192, k = i - n * 192;
        *(half*)(smem + SO_W1 + n * XSTR + k * 2) = __float2half_rn(W1[i]);
    }
    for (int i = tid; i < 64 * 128; i += 384) {
        int n = i >> 7, k = i & 127;
        *(half*)(smem + SO_W2 + n * HSTR + k * 2) = __float2half_rn(W2[i]);
    }
    if (tid < 128) ((float*)(smem + SO_B1))[tid] = b1[tid];
    if (tid < 64)  ((float*)(smem + SO_B2))[tid] = b2[tid];
    BARX(0, 384);

    const int ntiles = (E + 63) >> 6;
    const long long stride = 2LL * gridDim.x;
    const int g_half = lane >> 4;
    const int g_li   = lane & 15;

    if (w >= 8) {
        // =================== PRODUCERS ===================
        const int g  = (w - 8) >> 1;          // group 0/1
        const int pw = (w - 8) & 1;           // 32-row half
        const int rdy = 1 + 2 * g, csm = 2 + 2 * g;
        const uint32_t xg = sb + SO_X + (uint32_t)(2 * g) * XBUF;
        long long t0 = 2LL * blockIdx.x + g;
        if (t0 < ntiles)
            fill_half(xg, t0, pw, g_half, g_li, edges, node_state, edge_state, E);
        BARA(rdy, 192);                        // ready buf0
        int it = 0;
        for (long long t = t0; t < ntiles; t += stride, it++) {
            BARX(csm, 192);                    // consumers done GEMM1(it)
            long long tn = t + stride;
            if (tn < ntiles)
                fill_half(xg + (uint32_t)((it + 1) & 1) * XBUF, tn, pw,
                          g_half, g_li, edges, node_state, edge_state, E);
            BARA(rdy, 192);                    // ready buf[(it+1)&1]
        }
    } else {
        // =================== CONSUMERS ===================
        const int g  = w >> 2;                 // group 0/1
        const int ww = w & 3;                  // warp within group
        const int rdy = 1 + 2 * g, csm = 2 + 2 * g, hb = 5 + g;
        const uint32_t xg = sb + SO_X + (uint32_t)(2 * g) * XBUF;
        const uint32_t hg = sb + ((g == 0) ? SO_H0 : SO_H1);

        const int m0  = (ww & 1) * 32;         // 32 rows per warp
        const int n0  = (ww >> 1) * 64;        // GEMM1: 64 cols per warp
        const int n02 = (ww >> 1) * 32;        // GEMM2: 32 cols per warp

        float2 b1v[8], b2v[4];
        {
            const float* b1s = (const float*)(smem + SO_B1);
            const float* b2s = (const float*)(smem + SO_B2);
            int cb = 2 * (lane & 3);
#pragma unroll
            for (int nt = 0; nt < 8; nt++) {
                int c = n0 + nt * 8 + cb;
                b1v[nt] = make_float2(b1s[c], b1s[c + 1]);
            }
#pragma unroll
            for (int nt = 0; nt < 4; nt++) {
                int c = n02 + nt * 8 + cb;
                b2v[nt] = make_float2(b2s[c], b2s[c + 1]);
            }
        }

        const int a_r = lane & 15;
        const int a_c = (lane >> 4) << 3;
        const int b_r = ((lane >> 4) << 3) + (lane & 7);
        const int b_c = ((lane >> 3) & 1) << 3;

        uint32_t aXo[2], aH[2], bW1[4], bW2[2];
#pragma unroll
        for (int mt = 0; mt < 2; mt++) {
            aXo[mt] = (uint32_t)(m0 + mt * 16 + a_r) * XSTR + a_c * 2;
            aH[mt]  = hg + (uint32_t)(m0 + mt * 16 + a_r) * HSTR + a_c * 2;
        }
#pragma unroll
        for (int np = 0; np < 4; np++)
            bW1[np] = sb + SO_W1 + (uint32_t)(n0 + np * 16 + b_r) * XSTR + b_c * 2;
#pragma unroll
        for (int np = 0; np < 2; np++)
            bW2[np] = sb + SO_W2 + (uint32_t)(n02 + np * 16 + b_r) * HSTR + b_c * 2;

        const int act_r = lane >> 2;
        const int act_c = 2 * (lane & 3);

        int it = 0;
        for (long long t = 2LL * blockIdx.x + g; t < ntiles; t += stride, it++) {
            BARX(rdy, 192);                    // X buf[it&1] ready (also orders
                                               // prior tile's GEMM2 across group)
            uint32_t xb = xg + (uint32_t)(it & 1) * XBUF;

            // ============ GEMM1: 32x64, K=192 ============
            float acc[2][8][4];
#pragma unroll
            for (int mt = 0; mt < 2; mt++)
#pragma unroll
                for (int nt = 0; nt < 8; nt++)
#pragma unroll
                    for (int q = 0; q < 4; q++) acc[mt][nt][q] = 0.0f;

#pragma unroll
            for (int k = 0; k < 12; k++) {
                uint32_t A0[4], A1[4], B[4][4];
                ldm4(A0, xb + aXo[0] + k * 32);
                ldm4(A1, xb + aXo[1] + k * 32);
#pragma unroll
                for (int np = 0; np < 4; np++) ldm4(B[np], bW1[np] + k * 32);
#pragma unroll
                for (int np = 0; np < 4; np++) {
#pragma unroll
                    for (int h = 0; h < 2; h++) {
                        mma16816(acc[0][np * 2 + h], A0, B[np][2 * h], B[np][2 * h + 1]);
                        mma16816(acc[1][np * 2 + h], A1, B[np][2 * h], B[np][2 * h + 1]);
                    }
                }
            }
            BARA(csm, 192);                    // X buf[it&1] consumed

            // ============ activation -> f16 H ============
#pragma unroll
            for (int mt = 0; mt < 2; mt++) {
                uint32_t ha = hg + (uint32_t)(m0 + mt * 16 + act_r) * HSTR
                            + (uint32_t)(n0 + act_c) * 2;
#pragma unroll
                for (int nt = 0; nt < 8; nt++) {
                    float x0 = acc[mt][nt][0] + b1v[nt].x;
                    float x1 = acc[mt][nt][1] + b1v[nt].y;
                    float x2 = acc[mt][nt][2] + b1v[nt].x;
                    float x3 = acc[mt][nt][3] + b1v[nt].y;
                    uint32_t h01 = pkh2(ssp(x0), ssp(x1));
                    uint32_t h23 = pkh2(ssp(x2), ssp(x3));
                    asm volatile("st.shared.b32 [%0], %1;"
                                 :: "r"(ha + nt * 16), "r"(h01) : "memory");
                    asm volatile("st.shared.b32 [%0], %1;"
                                 :: "r"(ha + nt * 16 + 8 * HSTR), "r"(h23) : "memory");
                }
            }
            BARX(hb, 128);                     // group H ready

            // ============ GEMM2: 32x32, K=128 ============
            float acc2[2][4][4];
#pragma unroll
            for (int mt = 0; mt < 2; mt++)
#pragma unroll
                for (int nt = 0; nt < 4; nt++)
#pragma unroll
                    for (int q = 0; q < 4; q++) acc2[mt][nt][q] = 0.0f;

#pragma unroll
            for (int k = 0; k < 8; k++) {
                uint32_t A0[4], A1[4], B[2][4];
                ldm4(A0, aH[0] + k * 32);
                ldm4(A1, aH[1] + k * 32);
                ldm4(B[0], bW2[0] + k * 32);
                ldm4(B[1], bW2[1] + k * 32);
#pragma unroll
                for (int np = 0; np < 2; np++) {
#pragma unroll
                    for (int h = 0; h < 2; h++) {
                        mma16816(acc2[0][np * 2 + h], A0, B[np][2 * h], B[np][2 * h + 1]);
                        mma16816(acc2[1][np * 2 + h], A1, B[np][2 * h], B[np][2 * h + 1]);
                    }
                }
            }

            // ============ epilogue: out = D2 + b2 (streaming) ============
            {
                long long ebase = t * 64 + m0 + act_r;
#pragma unroll
                for (int mt = 0; mt < 2; mt++) {
                    long long r0e = ebase + mt * 16;
#pragma unroll
                    for (int nt = 0; nt < 4; nt++) {
                        int c = n02 + nt * 8 + act_c;
                        if (r0e < E) {
                            float2 v;
                            v.x = acc2[mt][nt][0] + b2v[nt].x;
                            v.y = acc2[mt][nt][1] + b2v[nt].y;
                            __stcs((float2*)(out + r0e * 64 + c), v);
                        }
                        if (r0e + 8 < E) {
                            float2 v;
                            v.x = acc2[mt][nt][2] + b2v[nt].x;
                            v.y = acc2[mt][nt][3] + b2v[nt].y;
                            __stcs((float2*)(out + (r0e + 8) * 64 + c), v);
                        }
                    }
                }
            }
        }
    }
}

extern "C" void kernel_launch(void* const* d_in, const int* in_sizes, int n_in,
                              void* d_out, int out_size) {
    const float* edge_state = (const float*)d_in[0];
    const int*   edges      = (const int*)d_in[1];
    const float* node_state = (const float*)d_in[2];
    const float* W1         = (const float*)d_in[3];
    const float* b1         = (const float*)d_in[4];
    const float* W2         = (const float*)d_in[5];
    const float* b2         = (const float*)d_in[6];
    float*       out        = (float*)d_out;
    int E = in_sizes[0] / 64;

    cudaFuncSetAttribute(edge_update_kernel,
                         cudaFuncAttributeMaxDynamicSharedMemorySize, SMEM_TOTAL);
    edge_update_kernel<<<148, 384, SMEM_TOTAL>>>(edge_state, edges, node_state,
                                                 W1, b1, W2, b2, out, E);
}

// round 8
// speedup vs baseline: 1.1359x; 1.1359x over previous
#include <cuda_runtime.h>
#include <cuda_fp16.h>
#include <cstdint>

// ============================================================
// EdgeUpdate fused MLP via legacy mma.sync (sm_103 non-'a' target).
// R8: register-fused GEMM1->act->GEMM2.
//   Consumer warp tile = 32 rows x FULL 128 cols for GEMM1, so the
//   m16n8k16 C-fragment of GEMM1 *is* the A-fragment of GEMM2
//   (identical per-thread layout). Activation applies in registers;
//   H never touches SMEM; no H barrier; GEMM2 A-ldmatrix eliminated.
//   4 consumer warps (1/SMSP) + 4 producer warps (gather, double-
//   buffered X). One bar.sync per tile.
// ============================================================

#define XSTR 400   // 192 f16 + pad
#define HSTR 272   // 128 f16 + pad (W2 rows)
#define XBUF (128 * XSTR)               // 51200 per X buffer

#define SO_X0  0
#define SO_X1  XBUF
#define SO_W1  (2 * XBUF)               // 51200
#define SO_W2  (SO_W1 + 128 * XSTR)     // 17408
#define SO_B1  (SO_W2 + 64 * HSTR)
#define SO_B2  (SO_B1 + 512)
#define SMEM_TOTAL (SO_B2 + 256 + 128)  // ~172 KB

#define BARX(id, cnt) \
    asm volatile("bar.sync %0, %1;" :: "r"(id), "r"(cnt) : "memory")

__device__ __forceinline__ uint32_t s2u(const void* p) {
    uint32_t a;
    asm("{ .reg .u64 t; cvta.to.shared.u64 t, %1; cvt.u32.u64 %0, t; }"
        : "=r"(a) : "l"(p));
    return a;
}

__device__ __forceinline__ uint32_t pkh2(float lo, float hi) {
    uint32_t r;
    asm("cvt.rn.f16x2.f32 %0, %1, %2;" : "=r"(r) : "f"(hi), "f"(lo));
    return r;
}

__device__ __forceinline__ void ldm4(uint32_t* r, uint32_t addr) {
    asm volatile("ldmatrix.sync.aligned.m8n8.x4.shared.b16 {%0,%1,%2,%3}, [%4];"
                 : "=r"(r[0]), "=r"(r[1]), "=r"(r[2]), "=r"(r[3]) : "r"(addr));
}

__device__ __forceinline__ void mma16816(float* d, const uint32_t* a,
                                         uint32_t b0, uint32_t b1) {
    asm volatile(
        "mma.sync.aligned.m16n8k16.row.col.f32.f16.f16.f32 "
        "{%0,%1,%2,%3}, {%4,%5,%6,%7}, {%8,%9}, {%0,%1,%2,%3};"
        : "+f"(d[0]), "+f"(d[1]), "+f"(d[2]), "+f"(d[3])
        : "r"(a[0]), "r"(a[1]), "r"(a[2]), "r"(a[3]), "r"(b0), "r"(b1));
}

// shifted softplus: softplus(x) - ln2 = max(x,0) + ln(1+e^{-|x|}) - ln2
__device__ __forceinline__ float ssp(float x) {
    float e = __expf(-fabsf(x));
    float l = __log2f(1.0f + e);
    return fmaxf(x, 0.0f) + 0.6931471805599453f * (l - 1.0f);
}

// producer: fill 32 rows (pw quarter) of a 128-row X buffer for `tile`
__device__ __forceinline__ void fill_q(
    uint32_t xb, long long tile, int pw, int g_half, int g_li,
    const int* __restrict__ edges, const float* __restrict__ node_state,
    const float* __restrict__ edge_state, int E) {
#pragma unroll 4
    for (int i2 = 0; i2 < 16; i2++) {
        int row = pw * 32 + i2 * 2 + g_half;
        long long e = tile * 128 + row;
        long long ec = (e < E) ? e : (long long)(E - 1);
        int2 np2 = ((const int2*)edges)[ec];
        uint32_t xr = xb + (uint32_t)row * XSTR + (uint32_t)g_li * 8u;
        float4 v0 = ((const float4*)(node_state + (long long)np2.x * 64))[g_li];
        float4 v1 = ((const float4*)(node_state + (long long)np2.y * 64))[g_li];
        float4 v2 = __ldcs((const float4*)(edge_state + ec * 64) + g_li);
        uint32_t a0 = pkh2(v0.x, v0.y), a1 = pkh2(v0.z, v0.w);
        uint32_t c0 = pkh2(v1.x, v1.y), c1 = pkh2(v1.z, v1.w);
        uint32_t d0 = pkh2(v2.x, v2.y), d1 = pkh2(v2.z, v2.w);
        asm volatile("st.shared.v2.b32 [%0], {%1,%2};"
                     :: "r"(xr), "r"(a0), "r"(a1) : "memory");
        asm volatile("st.shared.v2.b32 [%0], {%1,%2};"
                     :: "r"(xr + 128), "r"(c0), "r"(c1) : "memory");
        asm volatile("st.shared.v2.b32 [%0], {%1,%2};"
                     :: "r"(xr + 256), "r"(d0), "r"(d1) : "memory");
    }
}

__global__ void __launch_bounds__(256, 1)
edge_update_kernel(const float* __restrict__ edge_state,
                   const int* __restrict__ edges,
                   const float* __restrict__ node_state,
                   const float* __restrict__ W1, const float* __restrict__ b1,
                   const float* __restrict__ W2, const float* __restrict__ b2,
                   float* __restrict__ out, int E) {
    extern __shared__ __align__(128) char smem[];
    uint32_t sb = s2u(smem);
    int tid = threadIdx.x;
    int lane = tid & 31, w = tid >> 5;

    // ---- one-time: stage weights (f32 -> f16) + biases into SMEM ----
    for (int i = tid; i < 128 * 192; i += 256) {
        int n = i / 192, k = i - n * 192;
        *(half*)(smem + SO_W1 + n * XSTR + k * 2) = __float2half_rn(W1[i]);
    }
    for (int i = tid; i < 64 * 128; i += 256) {
        int n = i >> 7, k = i & 127;
        *(half*)(smem + SO_W2 + n * HSTR + k * 2) = __float2half_rn(W2[i]);
    }
    if (tid < 128) ((float*)(smem + SO_B1))[tid] = b1[tid];
    if (tid < 64)  ((float*)(smem + SO_B2))[tid] = b2[tid];
    BARX(0, 256);

    const int ntiles = (E + 127) >> 7;
    const int g_half = lane >> 4;
    const int g_li   = lane & 15;

    if (w >= 4) {
        // =================== PRODUCERS (warps 4-7) ===================
        const int pw = w - 4;
        long long t0 = blockIdx.x;
        if (t0 < ntiles)
            fill_q(sb + SO_X0, t0, pw, g_half, g_li, edges, node_state,
                   edge_state, E);
        int it = 0;
        for (long long t = t0; t < ntiles; t += gridDim.x, it++) {
            BARX(0, 256);   // buf[it&1] published; buf[(it+1)&1] free
            long long tn = t + gridDim.x;
            if (tn < ntiles)
                fill_q(sb + ((it & 1) ? SO_X0 : SO_X1), tn, pw, g_half, g_li,
                       edges, node_state, edge_state, E);
        }
    } else {
        // =================== CONSUMERS (warps 0-3) ===================
        const int m0 = w * 32;     // 32 rows per warp, full 128-col stripe

        const int a_r = lane & 15;
        const int a_c = (lane >> 4) << 3;
        const int b_r = ((lane >> 4) << 3) + (lane & 7);
        const int b_c = ((lane >> 3) & 1) << 3;
        const int cr  = lane >> 2;        // C-frag row
        const int cc2 = 2 * (lane & 3);   // C-frag col pair base

        uint32_t aXo[2];
#pragma unroll
        for (int mt = 0; mt < 2; mt++)
            aXo[mt] = (uint32_t)(m0 + mt * 16 + a_r) * XSTR + a_c * 2;
        uint32_t bW1[8];
#pragma unroll
        for (int np = 0; np < 8; np++)
            bW1[np] = sb + SO_W1 + (uint32_t)(np * 16 + b_r) * XSTR + b_c * 2;
        uint32_t bW2[4];
#pragma unroll
        for (int np = 0; np < 4; np++)
            bW2[np] = sb + SO_W2 + (uint32_t)(np * 16 + b_r) * HSTR + b_c * 2;

        const float* b1s = (const float*)(smem + SO_B1);
        const float* b2s = (const float*)(smem + SO_B2);

        int it = 0;
        for (long long t = blockIdx.x; t < ntiles; t += gridDim.x, it++) {
            BARX(0, 256);   // X buf[it&1] ready
            uint32_t xb = sb + ((it & 1) ? SO_X1 : SO_X0);

            // ============ GEMM1: 32x128, K=192 ============
            float acc[2][16][4];
#pragma unroll
            for (int mt = 0; mt < 2; mt++)
#pragma unroll
                for (int nt = 0; nt < 16; nt++)
#pragma unroll
                    for (int q = 0; q < 4; q++) acc[mt][nt][q] = 0.0f;

#pragma unroll
            for (int k = 0; k < 12; k++) {
                uint32_t A0[4], A1[4], B[8][4];
                ldm4(A0, xb + aXo[0] + k * 32);
                ldm4(A1, xb + aXo[1] + k * 32);
#pragma unroll
                for (int np = 0; np < 8; np++) ldm4(B[np], bW1[np] + k * 32);
#pragma unroll
                for (int np = 0; np < 8; np++) {
#pragma unroll
                    for (int h = 0; h < 2; h++) {
                        mma16816(acc[0][np * 2 + h], A0, B[np][2 * h], B[np][2 * h + 1]);
                        mma16816(acc[1][np * 2 + h], A1, B[np][2 * h], B[np][2 * h + 1]);
                    }
                }
            }

            // ==== fused act + GEMM2 (A-frag from GEMM1 C-frag, in regs) ====
            float acc2[2][8][4];
#pragma unroll
            for (int mt = 0; mt < 2; mt++)
#pragma unroll
                for (int nt = 0; nt < 8; nt++)
#pragma unroll
                    for (int q = 0; q < 4; q++) acc2[mt][nt][q] = 0.0f;

#pragma unroll
            for (int j = 0; j < 8; j++) {
                // biases for cols 16j+cc2 (lo pair) and 16j+8+cc2 (hi pair)
                float2 bl = *(const float2*)(b1s + 16 * j + cc2);
                float2 bh = *(const float2*)(b1s + 16 * j + 8 + cc2);
                uint32_t Af[2][4];
#pragma unroll
                for (int mt = 0; mt < 2; mt++) {
                    Af[mt][0] = pkh2(ssp(acc[mt][2 * j][0] + bl.x),
                                     ssp(acc[mt][2 * j][1] + bl.y));
                    Af[mt][1] = pkh2(ssp(acc[mt][2 * j][2] + bl.x),
                                     ssp(acc[mt][2 * j][3] + bl.y));
                    Af[mt][2] = pkh2(ssp(acc[mt][2 * j + 1][0] + bh.x),
                                     ssp(acc[mt][2 * j + 1][1] + bh.y));
                    Af[mt][3] = pkh2(ssp(acc[mt][2 * j + 1][2] + bh.x),
                                     ssp(acc[mt][2 * j + 1][3] + bh.y));
                }
                uint32_t B2[4][4];
#pragma unroll
                for (int np = 0; np < 4; np++) ldm4(B2[np], bW2[np] + j * 32);
#pragma unroll
                for (int np = 0; np < 4; np++) {
#pragma unroll
                    for (int h = 0; h < 2; h++) {
                        mma16816(acc2[0][np * 2 + h], Af[0],
                                 B2[np][2 * h], B2[np][2 * h + 1]);
                        mma16816(acc2[1][np * 2 + h], Af[1],
                                 B2[np][2 * h], B2[np][2 * h + 1]);
                    }
                }
            }

            // ============ epilogue: out = D2 + b2 (streaming) ============
            {
                long long ebase = t * 128 + m0 + cr;
#pragma unroll
                for (int mt = 0; mt < 2; mt++) {
                    long long r0e = ebase + mt * 16;
#pragma unroll
                    for (int nt = 0; nt < 8; nt++) {
                        int c = nt * 8 + cc2;
                        float2 bb = *(const float2*)(b2s + c);
                        if (r0e < E) {
                            float2 v;
                            v.x = acc2[mt][nt][0] + bb.x;
                            v.y = acc2[mt][nt][1] + bb.y;
                            __stcs((float2*)(out + r0e * 64 + c), v);
                        }
                        if (r0e + 8 < E) {
                            float2 v;
                            v.x = acc2[mt][nt][2] + bb.x;
                            v.y = acc2[mt][nt][3] + bb.y;
                            __stcs((float2*)(out + (r0e + 8) * 64 + c), v);
                        }
                    }
                }
            }
        }
    }
}

extern "C" void kernel_launch(void* const* d_in, const int* in_sizes, int n_in,
                              void* d_out, int out_size) {
    const float* edge_state = (const float*)d_in[0];
    const int*   edges      = (const int*)d_in[1];
    const float* node_state = (const float*)d_in[2];
    const float* W1         = (const float*)d_in[3];
    const float* b1         = (const float*)d_in[4];
    const float* W2         = (const float*)d_in[5];
    const float* b2         = (const float*)d_in[6];
    float*       out        = (float*)d_out;
    int E = in_sizes[0] / 64;

    cudaFuncSetAttribute(edge_update_kernel,
                         cudaFuncAttributeMaxDynamicSharedMemorySize, SMEM_TOTAL);
    edge_update_kernel<<<148, 256, SMEM_TOTAL>>>(edge_state, edges, node_state,
                                                 W1, b1, W2, b2, out, E);
}

// round 9
// speedup vs baseline: 1.1689x; 1.0290x over previous
#include <cuda_runtime.h>
#include <cuda_fp16.h>
#include <cstdint>

// ============================================================
// EdgeUpdate fused MLP via legacy mma.sync (sm_103 non-'a' target).
// R9: register-fused GEMM1->act->GEMM2 with 2 consumer warps/SMSP.
//   8 consumer warps x 16 rows (full 128-col stripe: GEMM1 C-frag
//   == GEMM2 A-frag per-thread layout, activation in registers,
//   no H SMEM round trip) + 4 producer warps (gather, double-
//   buffered X). Polynomial ln(1+t) replaces __log2f: 1 MUFU per
//   element instead of 2; poly runs on the idle FMA pipe.
// ============================================================

#define XSTR 400   // 192 f16 + pad
#define HSTR 272   // 128 f16 + pad (W2 rows)
#define XBUF (128 * XSTR)               // 51200 per X buffer

#define SO_X0  0
#define SO_X1  XBUF
#define SO_W1  (2 * XBUF)               // 51200
#define SO_W2  (SO_W1 + 128 * XSTR)     // 17408
#define SO_B1  (SO_W2 + 64 * HSTR)
#define SO_B2  (SO_B1 + 512)
#define SMEM_TOTAL (SO_B2 + 256 + 128)  // ~172 KB

#define BARX(id, cnt) \
    asm volatile("bar.sync %0, %1;" :: "r"(id), "r"(cnt) : "memory")

__device__ __forceinline__ uint32_t s2u(const void* p) {
    uint32_t a;
    asm("{ .reg .u64 t; cvta.to.shared.u64 t, %1; cvt.u32.u64 %0, t; }"
        : "=r"(a) : "l"(p));
    return a;
}

__device__ __forceinline__ uint32_t pkh2(float lo, float hi) {
    uint32_t r;
    asm("cvt.rn.f16x2.f32 %0, %1, %2;" : "=r"(r) : "f"(hi), "f"(lo));
    return r;
}

__device__ __forceinline__ void ldm4(uint32_t* r, uint32_t addr) {
    asm volatile("ldmatrix.sync.aligned.m8n8.x4.shared.b16 {%0,%1,%2,%3}, [%4];"
                 : "=r"(r[0]), "=r"(r[1]), "=r"(r[2]), "=r"(r[3]) : "r"(addr));
}

__device__ __forceinline__ void mma16816(float* d, const uint32_t* a,
                                         uint32_t b0, uint32_t b1) {
    asm volatile(
        "mma.sync.aligned.m16n8k16.row.col.f32.f16.f16.f32 "
        "{%0,%1,%2,%3}, {%4,%5,%6,%7}, {%8,%9}, {%0,%1,%2,%3};"
        : "+f"(d[0]), "+f"(d[1]), "+f"(d[2]), "+f"(d[3])
        : "r"(a[0]), "r"(a[1]), "r"(a[2]), "r"(a[3]), "r"(b0), "r"(b1));
}

// shifted softplus: max(x,0) + ln(1+e^{-|x|}) - ln2.
// ln(1+t), t in (0,1], via degree-5 Chebyshev-derived polynomial
// (abs err ~1e-5, far below the f16 quantization applied to H).
__device__ __forceinline__ float ssp(float x) {
    float t = __expf(-fabsf(x));
    float p = fmaf(0.0304544f, t, -0.1315984f);
    p = fmaf(p, t, 0.2852912f);
    p = fmaf(p, t, -0.4902392f);
    p = fmaf(p, t, 0.9992368f);
    return fmaf(p, t, fmaxf(x, 0.0f) - 0.6931472f);
}

// producer: fill 32 rows (pw quarter) of a 128-row X buffer for `tile`
__device__ __forceinline__ void fill_q(
    uint32_t xb, long long tile, int pw, int g_half, int g_li,
    const int* __restrict__ edges, const float* __restrict__ node_state,
    const float* __restrict__ edge_state, int E) {
#pragma unroll 4
    for (int i2 = 0; i2 < 16; i2++) {
        int row = pw * 32 + i2 * 2 + g_half;
        long long e = tile * 128 + row;
        long long ec = (e < E) ? e : (long long)(E - 1);
        int2 np2 = ((const int2*)edges)[ec];
        uint32_t xr = xb + (uint32_t)row * XSTR + (uint32_t)g_li * 8u;
        float4 v0 = ((const float4*)(node_state + (long long)np2.x * 64))[g_li];
        float4 v1 = ((const float4*)(node_state + (long long)np2.y * 64))[g_li];
        float4 v2 = __ldcs((const float4*)(edge_state + ec * 64) + g_li);
        uint32_t a0 = pkh2(v0.x, v0.y), a1 = pkh2(v0.z, v0.w);
        uint32_t c0 = pkh2(v1.x, v1.y), c1 = pkh2(v1.z, v1.w);
        uint32_t d0 = pkh2(v2.x, v2.y), d1 = pkh2(v2.z, v2.w);
        asm volatile("st.shared.v2.b32 [%0], {%1,%2};"
                     :: "r"(xr), "r"(a0), "r"(a1) : "memory");
        asm volatile("st.shared.v2.b32 [%0], {%1,%2};"
                     :: "r"(xr + 128), "r"(c0), "r"(c1) : "memory");
        asm volatile("st.shared.v2.b32 [%0], {%1,%2};"
                     :: "r"(xr + 256), "r"(d0), "r"(d1) : "memory");
    }
}

__global__ void __launch_bounds__(384, 1)
edge_update_kernel(const float* __restrict__ edge_state,
                   const int* __restrict__ edges,
                   const float* __restrict__ node_state,
                   const float* __restrict__ W1, const float* __restrict__ b1,
                   const float* __restrict__ W2, const float* __restrict__ b2,
                   float* __restrict__ out, int E) {
    extern __shared__ __align__(128) char smem[];
    uint32_t sb = s2u(smem);
    int tid = threadIdx.x;
    int lane = tid & 31, w = tid >> 5;

    // ---- one-time: stage weights (f32 -> f16) + biases into SMEM ----
    for (int i = tid; i < 128 * 192; i += 384) {
        int n = i / 192, k = i - n * 192;
        *(half*)(smem + SO_W1 + n * XSTR + k * 2) = __float2half_rn(W1[i]);
    }
    for (int i = tid; i < 64 * 128; i += 384) {
        int n = i >> 7, k = i & 127;
        *(half*)(smem + SO_W2 + n * HSTR + k * 2) = __float2half_rn(W2[i]);
    }
    if (tid < 128) ((float*)(smem + SO_B1))[tid] = b1[tid];
    if (tid < 64)  ((float*)(smem + SO_B2))[tid] = b2[tid];
    BARX(0, 384);

    const int ntiles = (E + 127) >> 7;
    const int g_half = lane >> 4;
    const int g_li   = lane & 15;

    if (w >= 8) {
        // =================== PRODUCERS (warps 8-11) ===================
        const int pw = w - 8;
        long long t0 = blockIdx.x;
        if (t0 < ntiles)
            fill_q(sb + SO_X0, t0, pw, g_half, g_li, edges, node_state,
                   edge_state, E);
        int it = 0;
        for (long long t = t0; t < ntiles; t += gridDim.x, it++) {
            BARX(0, 384);   // buf[it&1] published; buf[(it+1)&1] free
            long long tn = t + gridDim.x;
            if (tn < ntiles)
                fill_q(sb + ((it & 1) ? SO_X0 : SO_X1), tn, pw, g_half, g_li,
                       edges, node_state, edge_state, E);
        }
    } else {
        // =================== CONSUMERS (warps 0-7) ===================
        const int m0 = w * 16;     // 16 rows per warp, full 128-col stripe

        const int a_r = lane & 15;
        const int a_c = (lane >> 4) << 3;
        const int b_r = ((lane >> 4) << 3) + (lane & 7);
        const int b_c = ((lane >> 3) & 1) << 3;
        const int cr  = lane >> 2;        // C-frag row (0..7)
        const int cc2 = 2 * (lane & 3);   // C-frag col pair base

        const uint32_t aXo = (uint32_t)(m0 + a_r) * XSTR + a_c * 2;
        uint32_t bW1[8];
#pragma unroll
        for (int np = 0; np < 8; np++)
            bW1[np] = sb + SO_W1 + (uint32_t)(np * 16 + b_r) * XSTR + b_c * 2;
        uint32_t bW2[4];
#pragma unroll
        for (int np = 0; np < 4; np++)
            bW2[np] = sb + SO_W2 + (uint32_t)(np * 16 + b_r) * HSTR + b_c * 2;

        const float* b1s = (const float*)(smem + SO_B1);
        const float* b2s = (const float*)(smem + SO_B2);

        int it = 0;
        for (long long t = blockIdx.x; t < ntiles; t += gridDim.x, it++) {
            BARX(0, 384);   // X buf[it&1] ready
            uint32_t xb = sb + ((it & 1) ? SO_X1 : SO_X0);

            // ============ GEMM1: 16x128, K=192 ============
            float acc[16][4];
#pragma unroll
            for (int nt = 0; nt < 16; nt++)
#pragma unroll
                for (int q = 0; q < 4; q++) acc[nt][q] = 0.0f;

#pragma unroll
            for (int k = 0; k < 12; k++) {
                uint32_t A0[4], B[8][4];
                ldm4(A0, xb + aXo + k * 32);
#pragma unroll
                for (int np = 0; np < 8; np++) ldm4(B[np], bW1[np] + k * 32);
#pragma unroll
                for (int np = 0; np < 8; np++) {
#pragma unroll
                    for (int h = 0; h < 2; h++)
                        mma16816(acc[np * 2 + h], A0, B[np][2 * h], B[np][2 * h + 1]);
                }
            }

            // ==== fused act + GEMM2 (A-frag from GEMM1 C-frag, in regs) ====
            float acc2[8][4];
#pragma unroll
            for (int nt = 0; nt < 8; nt++)
#pragma unroll
                for (int q = 0; q < 4; q++) acc2[nt][q] = 0.0f;

#pragma unroll
            for (int j = 0; j < 8; j++) {
                float2 bl = *(const float2*)(b1s + 16 * j + cc2);
                float2 bh = *(const float2*)(b1s + 16 * j + 8 + cc2);
                uint32_t Af[4];
                Af[0] = pkh2(ssp(acc[2 * j][0] + bl.x),
                             ssp(acc[2 * j][1] + bl.y));
                Af[1] = pkh2(ssp(acc[2 * j][2] + bl.x),
                             ssp(acc[2 * j][3] + bl.y));
                Af[2] = pkh2(ssp(acc[2 * j + 1][0] + bh.x),
                             ssp(acc[2 * j + 1][1] + bh.y));
                Af[3] = pkh2(ssp(acc[2 * j + 1][2] + bh.x),
                             ssp(acc[2 * j + 1][3] + bh.y));
                uint32_t B2[4][4];
#pragma unroll
                for (int np = 0; np < 4; np++) ldm4(B2[np], bW2[np] + j * 32);
#pragma unroll
                for (int np = 0; np < 4; np++) {
#pragma unroll
                    for (int h = 0; h < 2; h++)
                        mma16816(acc2[np * 2 + h], Af,
                                 B2[np][2 * h], B2[np][2 * h + 1]);
                }
            }

            // ============ epilogue: out = D2 + b2 (streaming) ============
            {
                long long r0e = t * 128 + m0 + cr;
#pragma unroll
                for (int nt = 0; nt < 8; nt++) {
                    int c = nt * 8 + cc2;
                    float2 bb = *(const float2*)(b2s + c);
                    if (r0e < E) {
                        float2 v;
                        v.x = acc2[nt][0] + bb.x;
                        v.y = acc2[nt][1] + bb.y;
                        __stcs((float2*)(out + r0e * 64 + c), v);
                    }
                    if (r0e + 8 < E) {
                        float2 v;
                        v.x = acc2[nt][2] + bb.x;
                        v.y = acc2[nt][3] + bb.y;
                        __stcs((float2*)(out + (r0e + 8) * 64 + c), v);
                    }
                }
            }
        }
    }
}

extern "C" void kernel_launch(void* const* d_in, const int* in_sizes, int n_in,
                              void* d_out, int out_size) {
    const float* edge_state = (const float*)d_in[0];
    const int*   edges      = (const int*)d_in[1];
    const float* node_state = (const float*)d_in[2];
    const float* W1         = (const float*)d_in[3];
    const float* b1         = (const float*)d_in[4];
    const float* W2         = (const float*)d_in[5];
    const float* b2         = (const float*)d_in[6];
    float*       out        = (float*)d_out;
    int E = in_sizes[0] / 64;

    cudaFuncSetAttribute(edge_update_kernel,
                         cudaFuncAttributeMaxDynamicSharedMemorySize, SMEM_TOTAL);
    edge_update_kernel<<<148, 384, SMEM_TOTAL>>>(edge_state, edges, node_state,
                                                 W1, b1, W2, b2, out, E);
}